// round 4
// baseline (speedup 1.0000x reference)
#include <cuda_runtime.h>
#include <cstdint>

#define SAMPLE 8192
#define KNN 8
#define EPSV 1e-12f
// Sentinel for empty top-9 slots: d2 field = +inf (valid float), idx = ~0.
#define SENT 0x7F800000FFFFFFFFull

// g_P: (x, y, z, |p|^2) query side.
// g_Q: (-2x, -2y, -2z, |p|^2) tile side, so d2 = (wi+wj) + dot(q, p): 1 FADD + 3 FFMA.
__device__ float4 g_P[SAMPLE];
__device__ float4 g_Q[SAMPLE];
__device__ float4 g_S[SAMPLE];

__global__ void gather_kernel(const float* __restrict__ means,
                              const float* __restrict__ sh0,
                              const int* __restrict__ idx_raw) {
    int i = blockIdx.x * blockDim.x + threadIdx.x;
    if (i >= SAMPLE) return;
    // Detect int64 vs int32 index layout: little-endian int64 values < 2^31
    // have all odd int32 words zero.
    bool is64 = ((idx_raw[1] | idx_raw[3] | idx_raw[5] | idx_raw[7] |
                  idx_raw[9] | idx_raw[11] | idx_raw[13] | idx_raw[15]) == 0);
    long long j = is64 ? ((const long long*)idx_raw)[i] : (long long)idx_raw[i];
    float x = means[3 * j + 0];
    float y = means[3 * j + 1];
    float z = means[3 * j + 2];
    float sq = fmaf(z, z, fmaf(y, y, x * x));
    g_P[i] = make_float4(x, y, z, sq);
    g_Q[i] = make_float4(-2.f * x, -2.f * y, -2.f * z, sq);
    g_S[i] = make_float4(sh0[3 * j + 0], sh0[3 * j + 1], sh0[3 * j + 2], 0.f);
}

// One warp per query point. 8 warps (8 queries) per block share smem tiles.
__global__ void __launch_bounds__(256) knn_loss_kernel(float* __restrict__ out) {
    __shared__ float4 sQ[256];
    const int lane = threadIdx.x & 31;
    const int warp = threadIdx.x >> 5;
    const int i = blockIdx.x * 8 + warp;
    const float4 pi = g_P[i];

    // Per-lane sorted ascending top-9 of u64 keys: (d2_bits << 32) | j
    unsigned long long heap[9];
#pragma unroll
    for (int k = 0; k < 9; k++) heap[k] = SENT;
    // Warp-uniform accept threshold: min over lanes of each lane's 9th-best
    // d2 — a provable upper bound on the warp-global 9th-best. Refreshed on
    // the rare insert path so it is always the tightest valid bound.
    float w8 = __int_as_float(0x7f800000);

    for (int t = 0; t < SAMPLE; t += 256) {
        __syncthreads();
        sQ[threadIdx.x] = g_Q[t + threadIdx.x];
        __syncthreads();
#pragma unroll
        for (int u = 0; u < 8; u++) {
            float4 qj = sQ[u * 32 + lane];
            float d2 = qj.w + pi.w;
            d2 = fmaf(qj.x, pi.x, d2);
            d2 = fmaf(qj.y, pi.y, d2);
            d2 = fmaf(qj.z, pi.z, d2);
            // Warp-uniform branch around a VOTE: cannot be if-converted, so
            // the ~70-instruction insert body issues only when some lane
            // actually accepts (this was the R3 perf bug: nvcc flattened the
            // plain `if` into an unconditional 54-op select chain).
            if (__any_sync(0xFFFFFFFFu, d2 <= w8)) {
                if (d2 <= w8) {  // raw d2 <= clamped d2, so the test is safe
                    float d2c = fmaxf(d2, EPSV);
                    unsigned long long key =
                        ((unsigned long long)__float_as_uint(d2c) << 32) |
                        (unsigned)(t + u * 32 + lane);
                    if (key < heap[8]) {
                        unsigned long long cur = key;
#pragma unroll
                        for (int k = 0; k < 9; k++) {
                            unsigned long long h = heap[k];
                            bool lt = cur < h;
                            heap[k] = lt ? cur : h;
                            cur = lt ? h : cur;
                        }
                    }
                }
                // Refresh the warp-uniform threshold (rare path, cheap here).
                float l8 = __uint_as_float((unsigned)(heap[8] >> 32));
#pragma unroll
                for (int o = 16; o > 0; o >>= 1)
                    l8 = fminf(l8, __shfl_xor_sync(0xFFFFFFFFu, l8, o));
                w8 = l8;
            }
        }
    }

    // Warp merge: 9 rounds of butterfly min over each lane's list head.
    // >=9 real keys exist warp-wide (the global top-9 all pass the filter and
    // are retained); real keys are unique (distinct j), lists are sorted, so
    // the warp-min head is a real key and exactly one lane pops per round.
    unsigned long long mykey = SENT;
#pragma unroll
    for (int r = 0; r < 9; r++) {
        unsigned long long cand = heap[0];
        unsigned long long m = cand;
#pragma unroll
        for (int o = 16; o > 0; o >>= 1) {
            unsigned long long other = __shfl_xor_sync(0xFFFFFFFFu, m, o);
            m = (other < m) ? other : m;
        }
        if (cand == m) {
#pragma unroll
            for (int k = 0; k < 8; k++) heap[k] = heap[k + 1];
            heap[8] = SENT;
        }
        if (lane == r) mykey = m;
    }

    // Ranks 1..8 (rank 0 = self / tied duplicate, excluded like knn_idx[:,1:])
    float contrib = 0.f;
    if (lane >= 1 && lane <= KNN) {
        int j = (int)(mykey & 0xFFFFFFFFu);
        float d2 = __uint_as_float((unsigned)(mykey >> 32));
        float dist = sqrtf(d2);
        float w = __expf(-dist);
        float4 si = g_S[i];
        float4 sj = g_S[j];
        float dx = si.x - sj.x, dy = si.y - sj.y, dz = si.z - sj.z;
        contrib = w * (dx * dx + dy * dy + dz * dz);
    }
#pragma unroll
    for (int o = 16; o > 0; o >>= 1)
        contrib += __shfl_xor_sync(0xFFFFFFFFu, contrib, o);
    if (lane == 0)
        atomicAdd(out, contrib * (1.f / (float)(SAMPLE * KNN * 3)));
}

extern "C" void kernel_launch(void* const* d_in, const int* in_sizes, int n_in,
                              void* d_out, int out_size) {
    const float* means = (const float*)d_in[0];
    const float* sh0 = (const float*)d_in[1];
    const int* idx = (const int*)d_in[2];
    float* out = (float*)d_out;

    gather_kernel<<<SAMPLE / 256, 256>>>(means, sh0, idx);
    cudaMemsetAsync(out, 0, sizeof(float), 0);
    knn_loss_kernel<<<SAMPLE / 8, 256>>>(out);
}

// round 5
// speedup vs baseline: 4.9748x; 4.9748x over previous
#include <cuda_runtime.h>
#include <cstdint>

#define SAMPLE 8192
#define KNN 8
#define EPSV 1e-12f
#define CAP 760          // per-warp survivor buffer (8*760*8B = 47.5KB static smem)
#define SUB 512          // threshold subsample size (16 per lane)
// Sentinel for empty top-9 slots: d2 field = +inf (valid float), idx = ~0.
#define SENT 0x7F800000FFFFFFFFull

// g_P: (x, y, z, |p|^2) query side.
// g_Q: (-2x, -2y, -2z, |p|^2) candidate side: d2 = (wi+wj) + dot(q,p) = FADD + 3 FFMA.
__device__ float4 g_P[SAMPLE];
__device__ float4 g_Q[SAMPLE];
__device__ float4 g_S[SAMPLE];

__global__ void gather_kernel(const float* __restrict__ means,
                              const float* __restrict__ sh0,
                              const int* __restrict__ idx_raw) {
    int i = blockIdx.x * blockDim.x + threadIdx.x;
    if (i >= SAMPLE) return;
    // Detect int64 vs int32 index layout: little-endian int64 values < 2^31
    // have all odd int32 words zero.
    bool is64 = ((idx_raw[1] | idx_raw[3] | idx_raw[5] | idx_raw[7] |
                  idx_raw[9] | idx_raw[11] | idx_raw[13] | idx_raw[15]) == 0);
    long long j = is64 ? ((const long long*)idx_raw)[i] : (long long)idx_raw[i];
    float x = means[3 * j + 0];
    float y = means[3 * j + 1];
    float z = means[3 * j + 2];
    float sq = fmaf(z, z, fmaf(y, y, x * x));
    g_P[i] = make_float4(x, y, z, sq);
    g_Q[i] = make_float4(-2.f * x, -2.f * y, -2.f * z, sq);
    g_S[i] = make_float4(sh0[3 * j + 0], sh0[3 * j + 1], sh0[3 * j + 2], 0.f);
}

__device__ __forceinline__ void insert9(unsigned long long heap[9],
                                        unsigned long long key) {
    // Flat 9-step sorted insert; intentionally if-converted by nvcc into a
    // branch-free ISETP/SEL chain (used only on low-frequency paths).
    unsigned long long cur = key;
#pragma unroll
    for (int k = 0; k < 9; k++) {
        unsigned long long h = heap[k];
        bool lt = cur < h;
        heap[k] = lt ? cur : h;
        cur = lt ? h : cur;
    }
}

// One warp per query point; 8 warps per block.
__global__ void __launch_bounds__(256) knn_loss_kernel(float* __restrict__ out) {
    __shared__ unsigned long long buf[8][CAP];
    __shared__ unsigned int cnt[8];
    const int lane = threadIdx.x & 31;
    const int warp = threadIdx.x >> 5;
    const int i = blockIdx.x * 8 + warp;
    const float4 pi = g_P[i];
    const float4* __restrict__ Q = g_Q;

    if (lane == 0) cnt[warp] = 0;
    __syncwarp();

    unsigned long long heap[9];
#pragma unroll
    for (int k = 0; k < 9; k++) heap[k] = SENT;

    // ---- Phase 1: exact top-9 over candidates [0, SUB) -> threshold T ----
    // T = 9th smallest clamped d2 of the subsample >= true 9th-NN d2 (a
    // subset's k-th order stat bounds the full set's from above).
#pragma unroll 4
    for (int u = 0; u < SUB / 32; u++) {
        int j = u * 32 + lane;
        float4 qj = Q[j];
        float d2 = qj.w + pi.w;
        d2 = fmaf(qj.x, pi.x, d2);
        d2 = fmaf(qj.y, pi.y, d2);
        d2 = fmaf(qj.z, pi.z, d2);
        float d2c = fmaxf(d2, EPSV);
        insert9(heap, ((unsigned long long)__float_as_uint(d2c) << 32) |
                          (unsigned)j);
    }
    // 9-round pop-merge; the 9th popped value (r==8) is T. m is warp-uniform.
    float T;
    {
        unsigned long long m9 = 0;
#pragma unroll
        for (int r = 0; r < 9; r++) {
            unsigned long long cand = heap[0];
            unsigned long long m = cand;
#pragma unroll
            for (int o = 16; o > 0; o >>= 1) {
                unsigned long long other = __shfl_xor_sync(0xFFFFFFFFu, m, o);
                m = (other < m) ? other : m;
            }
            if (cand == m) {
#pragma unroll
                for (int k = 0; k < 8; k++) heap[k] = heap[k + 1];
                heap[8] = SENT;
            }
            if (r == 8) m9 = m;
        }
        T = __uint_as_float((unsigned)(m9 >> 32));
    }

    // ---- Phase 2: full scan, buffer survivors (raw d2 <= T; raw <= clamped,
    // so every true top-9 member is accepted) ----
#pragma unroll 1
    for (int t = 0; t < SAMPLE; t += 256) {
#pragma unroll
        for (int u = 0; u < 8; u++) {
            int j = t + u * 32 + lane;
            float4 qj = Q[j];
            float d2 = qj.w + pi.w;
            d2 = fmaf(qj.x, pi.x, d2);
            d2 = fmaf(qj.y, pi.y, d2);
            d2 = fmaf(qj.z, pi.z, d2);
            float d2c = fmaxf(d2, EPSV);
            if (d2 <= T) {
                unsigned slot = atomicAdd(&cnt[warp], 1u);
                if (slot < CAP)
                    buf[warp][slot] =
                        ((unsigned long long)__float_as_uint(d2c) << 32) |
                        (unsigned)j;
            }
        }
    }
    __syncwarp();

    // ---- Phase 3: exact top-9 over survivors ----
#pragma unroll
    for (int k = 0; k < 9; k++) heap[k] = SENT;
    unsigned n = cnt[warp];
    if (n > CAP) n = CAP;
    for (unsigned s = lane; s < n; s += 32) insert9(heap, buf[warp][s]);

    // Warp merge: survivors >= 9 (the subsample's top-9 all pass the filter),
    // keys unique (distinct j), lane lists sorted -> warp-min of heads is the
    // global min of the remainder for 9 rounds.
    unsigned long long mykey = SENT;
#pragma unroll
    for (int r = 0; r < 9; r++) {
        unsigned long long cand = heap[0];
        unsigned long long m = cand;
#pragma unroll
        for (int o = 16; o > 0; o >>= 1) {
            unsigned long long other = __shfl_xor_sync(0xFFFFFFFFu, m, o);
            m = (other < m) ? other : m;
        }
        if (cand == m) {
#pragma unroll
            for (int k = 0; k < 8; k++) heap[k] = heap[k + 1];
            heap[8] = SENT;
        }
        if (lane == r) mykey = m;
    }

    // Ranks 1..8 (rank 0 = self / tied duplicate, excluded like knn_idx[:,1:])
    float contrib = 0.f;
    if (lane >= 1 && lane <= KNN) {
        int j = (int)(mykey & 0xFFFFFFFFu);
        float d2 = __uint_as_float((unsigned)(mykey >> 32));
        float dist = sqrtf(d2);
        float w = __expf(-dist);
        float4 si = g_S[i];
        float4 sj = g_S[j];
        float dx = si.x - sj.x, dy = si.y - sj.y, dz = si.z - sj.z;
        contrib = w * (dx * dx + dy * dy + dz * dz);
    }
#pragma unroll
    for (int o = 16; o > 0; o >>= 1)
        contrib += __shfl_xor_sync(0xFFFFFFFFu, contrib, o);
    if (lane == 0)
        atomicAdd(out, contrib * (1.f / (float)(SAMPLE * KNN * 3)));
}

extern "C" void kernel_launch(void* const* d_in, const int* in_sizes, int n_in,
                              void* d_out, int out_size) {
    const float* means = (const float*)d_in[0];
    const float* sh0 = (const float*)d_in[1];
    const int* idx = (const int*)d_in[2];
    float* out = (float*)d_out;

    gather_kernel<<<SAMPLE / 256, 256>>>(means, sh0, idx);
    cudaMemsetAsync(out, 0, sizeof(float), 0);
    knn_loss_kernel<<<SAMPLE / 8, 256>>>(out);
}